// round 12
// baseline (speedup 1.0000x reference)
#include <cuda_runtime.h>

// SpanRepLayer: start / inner-maxpool / end span representations.
// B=2, NS=512, S=1024, H=128, MAX_W=16. Output (B, NS, 3H) fp32.
//
// Inputs (metadata order):
//   d_in[0]: token_reps (B, S, H)  float32
//   d_in[1]: span_ids   (B, NS, 2) int32   [start, end+1]
//   d_in[2]: span_masks (B, NS)    int32 (bool promoted)
// Output: (B, NS, 3H) float32
//
// CONVERGED FINAL FORM (established over R2..R11; best wall 6.56us, ncu ~5.2us):
//  - 8 warps per span, 1 span per 256-thr CTA, grid=1024 -> 64 warps/SM
//    (hardware occupancy cap), single wave. Warp concurrency was the only
//    lever that moved kernel time (ncu 7.2 -> 5.1us); the remainder is
//    launch/drain overhead + two dependent memory epochs (ids -> rows,
//    addresses are data-dependent and irreducible) + wave spread.
//  - warps 0-3: start row + full inner max (14 predicated loads), write
//    start & inner thirds. warps 4-7: end row only, retire early freeing
//    issue slots.
//  - Predicated (not clamped) loads: off-range lanes contribute -inf, no
//    redundant L1tex wavefronts. No barrier, no smem: every warp is an
//    independent straight-line dependency chain.
//  - Plain stores (.cs regressed; working set ~2.5MB << 126MB L2).

#define SRL_NS 512
#define SRL_S  1024
#define SRL_NSPANS (2 * SRL_NS)
#define MAX_INNER 14
#define NEG_INF -3.0e38f

__global__ __launch_bounds__(256) void span_rep_kernel(
    const float* __restrict__ token_reps,
    const int2* __restrict__ span_ids,
    const int* __restrict__ span_masks,
    float* __restrict__ out)
{
    const int span = blockIdx.x;
    const int wib  = threadIdx.x >> 5;       // 0..7
    const int g    = wib >> 2;               // group 0/1
    const int lane = threadIdx.x & 31;
    const int ch   = (wib & 3) * 32 + lane;  // 0..127 channel

    // Independent scalar loads issued together (overlapped latency).
    const int  mask_i = span_masks[span];
    const int2 ids    = span_ids[span];
    const float m     = mask_i ? 1.0f : 0.0f;

    const int start = ids.x;
    const int end   = ids.y - 1;             // inclusive
    const int inner_len = end - start - 1;   // may be <= 0

    const int b = span >> 9;
    const float* __restrict__ base = token_reps + (size_t)b * SRL_S * 128 + ch;

    float* o = out + (size_t)span * 384;     // 3H = 384 floats

    if (g == 1) {
        // End third only: shortest possible chain, retire early.
        const float er = base[end * 128];
        o[ch + 256] = er * m;
        return;
    }

    // group0: start row + full inner max.
    const float sr = base[start * 128];

    float inner = NEG_INF;
    #pragma unroll
    for (int i = 0; i < MAX_INNER; ++i) {
        float vi = (i < inner_len) ? base[(start + 1 + i) * 128] : NEG_INF;
        inner = fmaxf(inner, vi);
    }
    if (inner_len <= 0) inner = sr;          // no inner tokens -> start rep

    o[ch]       = sr * m;
    o[ch + 128] = inner * m;
}

extern "C" void kernel_launch(void* const* d_in, const int* in_sizes, int n_in,
                              void* d_out, int out_size)
{
    const float* token_reps = (const float*)d_in[0];
    const int2* span_ids    = (const int2*)d_in[1];
    const int* span_masks   = (const int*)d_in[2];
    float* out              = (float*)d_out;

    // 1 span per CTA, 8 warps each -> 1024 CTAs, 8192 warps (64/SM, single wave).
    span_rep_kernel<<<SRL_NSPANS, 256>>>(token_reps, span_ids, span_masks, out);
}

// round 13
// speedup vs baseline: 1.0297x; 1.0297x over previous
#include <cuda_runtime.h>

// SpanRepLayer: start / inner-maxpool / end span representations.
// B=2, NS=512, S=1024, H=128, MAX_W=16. Output (B, NS, 3H) fp32.
//
// Inputs (metadata order):
//   d_in[0]: token_reps (B, S, H)  float32
//   d_in[1]: span_ids   (B, NS, 2) int32   [start, end+1]
//   d_in[2]: span_masks (B, NS)    int32 (bool promoted)
// Output: (B, NS, 3H) float32
//
// CONVERGED FINAL FORM (R2..R12; best wall 6.56us, ncu ~5.2us):
//  - 8 warps per span, 1 span per 256-thr CTA, grid=1024 -> 64 warps/SM
//    (hardware occupancy cap), single wave. Warp concurrency was the only
//    lever that moved kernel time (ncu 7.2 -> 5.1us); the remainder is
//    launch/drain overhead + two dependent memory epochs (ids -> rows,
//    data-dependent addresses, irreducible) + wave spread, plus a fixed
//    ~1.3us graph-replay overhead in the wall number.
//  - warps 0-3: start row + full inner max (14 predicated loads), write
//    start & inner thirds. warps 4-7: end row only, retire early freeing
//    issue slots.
//  - Predicated (not clamped) loads: off-range lanes contribute -inf, no
//    redundant L1tex wavefronts. No barrier, no smem: every warp is an
//    independent straight-line dependency chain.
//  - Plain stores (.cs regressed; working set ~2.5MB << 126MB L2).

#define SRL_NS 512
#define SRL_S  1024
#define SRL_NSPANS (2 * SRL_NS)
#define MAX_INNER 14
#define NEG_INF -3.0e38f

__global__ __launch_bounds__(256) void span_rep_kernel(
    const float* __restrict__ token_reps,
    const int2* __restrict__ span_ids,
    const int* __restrict__ span_masks,
    float* __restrict__ out)
{
    const int span = blockIdx.x;
    const int wib  = threadIdx.x >> 5;       // 0..7
    const int g    = wib >> 2;               // group 0/1
    const int lane = threadIdx.x & 31;
    const int ch   = (wib & 3) * 32 + lane;  // 0..127 channel

    // Independent scalar loads issued together (overlapped latency).
    const int  mask_i = span_masks[span];
    const int2 ids    = span_ids[span];
    const float m     = mask_i ? 1.0f : 0.0f;

    const int start = ids.x;
    const int end   = ids.y - 1;             // inclusive
    const int inner_len = end - start - 1;   // may be <= 0

    const int b = span >> 9;
    const float* __restrict__ base = token_reps + (size_t)b * SRL_S * 128 + ch;

    float* o = out + (size_t)span * 384;     // 3H = 384 floats

    if (g == 1) {
        // End third only: shortest possible chain, retire early.
        const float er = base[end * 128];
        o[ch + 256] = er * m;
        return;
    }

    // group0: start row + full inner max.
    const float sr = base[start * 128];

    float inner = NEG_INF;
    #pragma unroll
    for (int i = 0; i < MAX_INNER; ++i) {
        float vi = (i < inner_len) ? base[(start + 1 + i) * 128] : NEG_INF;
        inner = fmaxf(inner, vi);
    }
    if (inner_len <= 0) inner = sr;          // no inner tokens -> start rep

    o[ch]       = sr * m;
    o[ch + 128] = inner * m;
}

extern "C" void kernel_launch(void* const* d_in, const int* in_sizes, int n_in,
                              void* d_out, int out_size)
{
    const float* token_reps = (const float*)d_in[0];
    const int2* span_ids    = (const int2*)d_in[1];
    const int* span_masks   = (const int*)d_in[2];
    float* out              = (float*)d_out;

    // 1 span per CTA, 8 warps each -> 1024 CTAs, 8192 warps (64/SM, single wave).
    span_rep_kernel<<<SRL_NSPANS, 256>>>(token_reps, span_ids, span_masks, out);
}